// round 16
// baseline (speedup 1.0000x reference)
#include <cuda_runtime.h>
#include <cuda_bf16.h>
#include <cstdint>

// ---------------------------------------------------------------------------
// GCN graph conv, CSR two-phase aggregation + split-bf16 mma.sync GEMM.
//   h = tanh((feat*outdeg^-.5) @ W)  via 3-term bf16 split (HMMA, f32 acc)
//   out[n] = (sum_{e: dst=n} h[src_e]*ew_e) * indeg^-.5   (CSR gather)
// src/dst are INT32 on device (jax x64 disabled) despite int64 annotation.
// tcgen05 unavailable (harness targets sm_103, not 103a) -> mma.sync path.
// GEMM: R10 scalar-LDS 73.7KB layout — empirically beats BK16-DB, 208KB
// stage-B-once (occupancy collapse), and ldmatrix (+90us) variants. Do not
// touch the inner loops. Degree arrays self-cleaned by aggregate (no zero_deg).
// ---------------------------------------------------------------------------

#define IN_FEATS  256
#define OUT_FEATS 128
#define MAX_N     100000
#define MAX_E     1600000

__device__ int  g_outdeg[MAX_N];   // zeroed at module load; re-zeroed by aggregate
__device__ int  g_indeg [MAX_N];
__device__ int  g_start [MAX_N];
__device__ int  g_cursor[MAX_N];
__device__ int  g_bsum  [128];
__device__ __align__(8)  int2  g_edge[MAX_E];              // {src, f32 ew bits}
__device__ __align__(16) float g_h[(size_t)MAX_N * OUT_FEATS];
// W transposed + bf16-split: Wt[n][k] = W[k][n]
__device__ __align__(16) __nv_bfloat16 g_Wt_hi[OUT_FEATS * IN_FEATS];
__device__ __align__(16) __nv_bfloat16 g_Wt_lo[OUT_FEATS * IN_FEATS];

// ======================= graph-prep kernels =================================
__global__ void degree_kernel(const int* __restrict__ src,
                              const int* __restrict__ dst, int E) {
    int e = blockIdx.x * blockDim.x + threadIdx.x;
    if (e < E) {
        atomicAdd(&g_outdeg[src[e]], 1);
        atomicAdd(&g_indeg [dst[e]], 1);
    }
}

__global__ void scan_block_kernel(int n) {           // grid=ceil(n/1024), block=1024
    __shared__ int sh[1024];
    const int tid = threadIdx.x;
    const int i = blockIdx.x * 1024 + tid;
    int v = (i < n) ? g_indeg[i] : 0;
    sh[tid] = v;
    __syncthreads();
#pragma unroll
    for (int off = 1; off < 1024; off <<= 1) {
        int t = (tid >= off) ? sh[tid - off] : 0;
        __syncthreads();
        sh[tid] += t;
        __syncthreads();
    }
    if (i < n) g_start[i] = sh[tid] - v;             // exclusive within block
    if (tid == 1023) g_bsum[blockIdx.x] = sh[1023];  // block total
}

// Adds prefix of g_bsum[0..bid) computed in-block (nb <= 128). Replaces the
// separate scan_bsums kernel (one fewer launch; validated in R15).
__global__ void scan_add_kernel(int n, int nb) {     // block=1024
    __shared__ int sh[128];
    const int tid = threadIdx.x;
    if (tid < 128) {
        int v = (tid < nb && tid < blockIdx.x) ? g_bsum[tid] : 0;
        sh[tid] = v;
    }
    __syncthreads();
#pragma unroll
    for (int off = 64; off > 0; off >>= 1) {
        if (tid < off) sh[tid] += sh[tid + off];
        __syncthreads();
    }
    const int boff = sh[0];
    int i = blockIdx.x * 1024 + tid;
    if (i < n) {
        int s = g_start[i] + boff;
        g_start[i]  = s;
        g_cursor[i] = s;
    }
}

__global__ void fill_kernel(const int* __restrict__ src,
                            const int* __restrict__ dst,
                            const float* __restrict__ ew, int E) {
    int e = blockIdx.x * blockDim.x + threadIdx.x;
    if (e < E) {
        int d = dst[e];
        int slot = atomicAdd(&g_cursor[d], 1);
        g_edge[slot] = make_int2(src[e], __float_as_int(ew[e]));
    }
}

// W[256][128] f32 -> transposed split bf16 Wt[n][k]
__global__ void wsplit_kernel(const float* __restrict__ W) {
    int idx = blockIdx.x * blockDim.x + threadIdx.x;
    if (idx < IN_FEATS * OUT_FEATS) {
        int k = idx >> 7;            // 0..255
        int n = idx & 127;           // 0..127
        float x = W[idx];
        __nv_bfloat16 hi = __float2bfloat16(x);
        float lo = x - __bfloat162float(hi);
        g_Wt_hi[n * IN_FEATS + k] = hi;
        g_Wt_lo[n * IN_FEATS + k] = __float2bfloat16(lo);
    }
}

// ======================= split-bf16 mma.sync GEMM (R10, verbatim) ===========
// CTA: 128x128 tile, 8 warps (2m x 4n), warp tile 64x32, K chunks of 64.
// Smem tiles padded to 72 elems/row -> conflict-free 32-bit fragment LDS.
#define KC       64
#define NCHUNK   (IN_FEATS / KC)     // 4
#define TSTRIDE  72                  // elements per smem row (pad 64+8)
#define TROWB    (TSTRIDE * 2)       // 144 bytes
#define TILE_B   (128 * TROWB)       // 18432 bytes per tile
#define SM_AHI   0
#define SM_ALO   (SM_AHI + TILE_B)
#define SM_BHI   (SM_ALO + TILE_B)
#define SM_BLO   (SM_BHI + TILE_B)
#define SM_TOT   (SM_BLO + TILE_B)   // 73728 bytes

__device__ __forceinline__ uint32_t pack2bf(float a, float b) {
    __nv_bfloat162 t = __floats2bfloat162_rn(a, b);
    return *reinterpret_cast<uint32_t*>(&t);
}

#define MMA_BF16(c, a, b)                                                     \
    asm volatile(                                                             \
        "mma.sync.aligned.m16n8k16.row.col.f32.bf16.bf16.f32 "                \
        "{%0,%1,%2,%3}, {%4,%5,%6,%7}, {%8,%9}, {%0,%1,%2,%3};"               \
        : "+f"((c)[0]), "+f"((c)[1]), "+f"((c)[2]), "+f"((c)[3])              \
        : "r"((a)[0]), "r"((a)[1]), "r"((a)[2]), "r"((a)[3]),                 \
          "r"((b)[0]), "r"((b)[1]))

__global__ __launch_bounds__(256)
void gemm_mma_kernel(const float* __restrict__ feat, int M) {
    extern __shared__ __align__(16) char dsm[];
    const int tid  = threadIdx.x;
    const int lane = tid & 31;
    const int w    = tid >> 5;
    const int g    = lane >> 2;       // 0..7
    const int t    = lane & 3;        // 0..3
    const int m0   = (w >> 2) * 64;   // warp m-offset in tile
    const int n0   = (w & 3) * 32;    // warp n-offset in tile
    const int row0 = blockIdx.x * 128;

    // staging assignment: thread covers (row = tid/2, khalf = (tid&1)*32)
    const int srow = tid >> 1;
    const int skh  = (tid & 1) * 32;
    const bool rok = (row0 + srow) < M;
    float ascale = 0.0f;
    if (rok) {
        int dg = g_outdeg[row0 + srow];
        ascale = rsqrtf((float)(dg > 0 ? dg : 1));
    }

    float acc[4][4][4];
#pragma unroll
    for (int i = 0; i < 4; ++i)
#pragma unroll
        for (int j = 0; j < 4; ++j)
#pragma unroll
            for (int q = 0; q < 4; ++q) acc[i][j][q] = 0.0f;

#pragma unroll 1
    for (int c = 0; c < NCHUNK; ++c) {
        // ---- stage A (f32 -> bf16 hi/lo with ascale) ----
        {
            const float* ap = feat + (size_t)(row0 + srow) * IN_FEATS + c * KC + skh;
            char* dsthi = dsm + SM_AHI + srow * TROWB + skh * 2;
            char* dstlo = dsm + SM_ALO + srow * TROWB + skh * 2;
#pragma unroll
            for (int i = 0; i < 4; ++i) {            // 4 x 8 elems
                float4 f0 = make_float4(0.f, 0.f, 0.f, 0.f);
                float4 f1 = make_float4(0.f, 0.f, 0.f, 0.f);
                if (rok) {
                    f0 = __ldg((const float4*)(ap + i * 8));
                    f1 = __ldg((const float4*)(ap + i * 8 + 4));
                }
                f0.x *= ascale; f0.y *= ascale; f0.z *= ascale; f0.w *= ascale;
                f1.x *= ascale; f1.y *= ascale; f1.z *= ascale; f1.w *= ascale;
                float h[8] = {f0.x, f0.y, f0.z, f0.w, f1.x, f1.y, f1.z, f1.w};
                uint4 hv, lv;
                float hi0, hi1;
                hi0 = __bfloat162float(__float2bfloat16(h[0]));
                hi1 = __bfloat162float(__float2bfloat16(h[1]));
                hv.x = pack2bf(h[0], h[1]); lv.x = pack2bf(h[0]-hi0, h[1]-hi1);
                hi0 = __bfloat162float(__float2bfloat16(h[2]));
                hi1 = __bfloat162float(__float2bfloat16(h[3]));
                hv.y = pack2bf(h[2], h[3]); lv.y = pack2bf(h[2]-hi0, h[3]-hi1);
                hi0 = __bfloat162float(__float2bfloat16(h[4]));
                hi1 = __bfloat162float(__float2bfloat16(h[5]));
                hv.z = pack2bf(h[4], h[5]); lv.z = pack2bf(h[4]-hi0, h[5]-hi1);
                hi0 = __bfloat162float(__float2bfloat16(h[6]));
                hi1 = __bfloat162float(__float2bfloat16(h[7]));
                hv.w = pack2bf(h[6], h[7]); lv.w = pack2bf(h[6]-hi0, h[7]-hi1);
                *(uint4*)(dsthi + i * 16) = hv;
                *(uint4*)(dstlo + i * 16) = lv;
            }
        }
        // ---- stage B (preconverted bf16; Wt row n = srow) ----
        {
            const __nv_bfloat16* bh = g_Wt_hi + srow * IN_FEATS + c * KC + skh;
            const __nv_bfloat16* bl = g_Wt_lo + srow * IN_FEATS + c * KC + skh;
            char* dsthi = dsm + SM_BHI + srow * TROWB + skh * 2;
            char* dstlo = dsm + SM_BLO + srow * TROWB + skh * 2;
#pragma unroll
            for (int i = 0; i < 4; ++i) {            // 4 x uint4 = 32 bf16
                *(uint4*)(dsthi + i * 16) = __ldg((const uint4*)(bh + i * 8));
                *(uint4*)(dstlo + i * 16) = __ldg((const uint4*)(bl + i * 8));
            }
        }
        __syncthreads();

        // ---- compute: 4 k16 steps ----
#pragma unroll
        for (int ks = 0; ks < 4; ++ks) {
            uint32_t ah[4][4], al[4][4];
#pragma unroll
            for (int mf = 0; mf < 4; ++mf) {
                int ro = (m0 + mf * 16 + g) * TROWB + ks * 32 + t * 4;
                ah[mf][0] = *(const uint32_t*)(dsm + SM_AHI + ro);
                ah[mf][1] = *(const uint32_t*)(dsm + SM_AHI + ro + 8 * TROWB);
                ah[mf][2] = *(const uint32_t*)(dsm + SM_AHI + ro + 16);
                ah[mf][3] = *(const uint32_t*)(dsm + SM_AHI + ro + 8 * TROWB + 16);
                al[mf][0] = *(const uint32_t*)(dsm + SM_ALO + ro);
                al[mf][1] = *(const uint32_t*)(dsm + SM_ALO + ro + 8 * TROWB);
                al[mf][2] = *(const uint32_t*)(dsm + SM_ALO + ro + 16);
                al[mf][3] = *(const uint32_t*)(dsm + SM_ALO + ro + 8 * TROWB + 16);
            }
            uint32_t bh[4][2], bl[4][2];
#pragma unroll
            for (int nf = 0; nf < 4; ++nf) {
                int no = (n0 + nf * 8 + g) * TROWB + ks * 32 + t * 4;
                bh[nf][0] = *(const uint32_t*)(dsm + SM_BHI + no);
                bh[nf][1] = *(const uint32_t*)(dsm + SM_BHI + no + 16);
                bl[nf][0] = *(const uint32_t*)(dsm + SM_BLO + no);
                bl[nf][1] = *(const uint32_t*)(dsm + SM_BLO + no + 16);
            }
#pragma unroll
            for (int mf = 0; mf < 4; ++mf)
#pragma unroll
                for (int nf = 0; nf < 4; ++nf) {
                    MMA_BF16(acc[mf][nf], ah[mf], bh[nf]);
                    MMA_BF16(acc[mf][nf], ah[mf], bl[nf]);
                    MMA_BF16(acc[mf][nf], al[mf], bh[nf]);
                }
        }
        __syncthreads();
    }

    // ---- epilogue: tanh -> g_h ----
#pragma unroll
    for (int mf = 0; mf < 4; ++mf) {
        int r0g = row0 + m0 + mf * 16 + g;
        int r1g = r0g + 8;
#pragma unroll
        for (int nf = 0; nf < 4; ++nf) {
            int col = n0 + nf * 8 + t * 2;
            if (r0g < M) {
                float2 o;
                o.x = tanhf(acc[mf][nf][0]);
                o.y = tanhf(acc[mf][nf][1]);
                *(float2*)(g_h + (size_t)r0g * OUT_FEATS + col) = o;
            }
            if (r1g < M) {
                float2 o;
                o.x = tanhf(acc[mf][nf][2]);
                o.y = tanhf(acc[mf][nf][3]);
                *(float2*)(g_h + (size_t)r1g * OUT_FEATS + col) = o;
            }
        }
    }
}

// ======================= aggregate (R10 loop + self-clean) ==================
// One warp per dst node, lane owns one float4. 2-way unrolled gather.
__global__ __launch_bounds__(256)
void aggregate_kernel(float* __restrict__ out, int N) {
    const int lane = threadIdx.x & 31;
    const int n = blockIdx.x * (blockDim.x >> 5) + (threadIdx.x >> 5);
    if (n >= N) return;

    const int begin = g_start[n];
    const int cnt   = g_indeg[n];
    if (lane == 0) { g_indeg[n] = 0; g_outdeg[n] = 0; }   // clean for next call

    float4 acc = make_float4(0.f, 0.f, 0.f, 0.f);
    const float4* h4 = (const float4*)g_h;

    int j = 0;
    for (; j + 2 <= cnt; j += 2) {
        int2 e0 = g_edge[begin + j];
        int2 e1 = g_edge[begin + j + 1];
        float4 v0 = __ldg(h4 + (size_t)e0.x * (OUT_FEATS / 4) + lane);
        float4 v1 = __ldg(h4 + (size_t)e1.x * (OUT_FEATS / 4) + lane);
        float w0 = __int_as_float(e0.y);
        float w1 = __int_as_float(e1.y);
        acc.x = fmaf(v0.x, w0, acc.x); acc.y = fmaf(v0.y, w0, acc.y);
        acc.z = fmaf(v0.z, w0, acc.z); acc.w = fmaf(v0.w, w0, acc.w);
        acc.x = fmaf(v1.x, w1, acc.x); acc.y = fmaf(v1.y, w1, acc.y);
        acc.z = fmaf(v1.z, w1, acc.z); acc.w = fmaf(v1.w, w1, acc.w);
    }
    if (j < cnt) {
        int2 e0 = g_edge[begin + j];
        float4 v0 = __ldg(h4 + (size_t)e0.x * (OUT_FEATS / 4) + lane);
        float w0 = __int_as_float(e0.y);
        acc.x = fmaf(v0.x, w0, acc.x); acc.y = fmaf(v0.y, w0, acc.y);
        acc.z = fmaf(v0.z, w0, acc.z); acc.w = fmaf(v0.w, w0, acc.w);
    }

    const float sc = rsqrtf((float)(cnt > 0 ? cnt : 1));
    acc.x *= sc; acc.y *= sc; acc.z *= sc; acc.w *= sc;
    ((float4*)(out + (size_t)n * OUT_FEATS))[lane] = acc;
}

// ---------------------------------------------------------------------------
extern "C" void kernel_launch(void* const* d_in, const int* in_sizes, int n_in,
                              void* d_out, int out_size) {
    const float* feat = (const float*)d_in[0];
    const float* W    = (const float*)d_in[1];
    const float* ew   = (const float*)d_in[2];
    const int*   src  = (const int*)d_in[3];   // int32 on device
    const int*   dst  = (const int*)d_in[4];
    float*       out  = (float*)d_out;

    const int M = in_sizes[0] / IN_FEATS;   // 100000
    const int E = in_sizes[2];              // 1600000
    const int nb = (M + 1023) / 1024;       // 98 scan blocks

    cudaFuncSetAttribute(gemm_mma_kernel,
                         cudaFuncAttributeMaxDynamicSharedMemorySize, SM_TOT);

    degree_kernel<<<(E + 255) / 256, 256>>>(src, dst, E);
    scan_block_kernel<<<nb, 1024>>>(M);
    scan_add_kernel<<<nb, 1024>>>(M, nb);
    fill_kernel<<<(E + 255) / 256, 256>>>(src, dst, ew, E);
    wsplit_kernel<<<(IN_FEATS * OUT_FEATS + 255) / 256, 256>>>(W);
    gemm_mma_kernel<<<(M + 127) / 128, 256, SM_TOT>>>(feat, M);
    {
        const int warps_per_block = 256 / 32;
        const int blocks = (M + warps_per_block - 1) / warps_per_block;
        aggregate_kernel<<<blocks, 256>>>(out, M);
    }
}

// round 17
// speedup vs baseline: 1.4758x; 1.4758x over previous
#include <cuda_runtime.h>
#include <cuda_bf16.h>
#include <cstdint>

// ---------------------------------------------------------------------------
// GCN graph conv, CSR two-phase aggregation + split-bf16 mma.sync GEMM.
//   h = tanh((feat*outdeg^-.5) @ W)  via 3-term bf16 split (HMMA, f32 acc)
//   out[n] = (sum_{e: dst=n} h[src_e]*ew_e) * indeg^-.5   (CSR gather)
// src/dst are INT32 on device (jax x64 disabled) despite int64 annotation.
// tcgen05 unavailable (harness targets sm_103, not 103a) -> mma.sync path.
// EXACT R10 configuration (217.6us anchor). Known-bad variants: BK16-DB GEMM,
// 208KB stage-B-once (occupancy collapse), ldmatrix loads, self-clean/merged
// scan plumbing (R15/R16 ~320us). Do not reintroduce without single-variable
// evidence.
// ---------------------------------------------------------------------------

#define IN_FEATS  256
#define OUT_FEATS 128
#define MAX_N     100000
#define MAX_E     1600000

__device__ int  g_outdeg[MAX_N];
__device__ int  g_indeg [MAX_N];
__device__ int  g_start [MAX_N];
__device__ int  g_cursor[MAX_N];
__device__ int  g_bsum  [128];
__device__ __align__(8)  int2  g_edge[MAX_E];              // {src, f32 ew bits}
__device__ __align__(16) float g_h[(size_t)MAX_N * OUT_FEATS];
// W transposed + bf16-split: Wt[n][k] = W[k][n]
__device__ __align__(16) __nv_bfloat16 g_Wt_hi[OUT_FEATS * IN_FEATS];
__device__ __align__(16) __nv_bfloat16 g_Wt_lo[OUT_FEATS * IN_FEATS];

// ======================= graph-prep kernels =================================
__global__ void zero_deg_kernel(int n) {
    int i = blockIdx.x * blockDim.x + threadIdx.x;
    if (i < n) { g_outdeg[i] = 0; g_indeg[i] = 0; }
}

__global__ void degree_kernel(const int* __restrict__ src,
                              const int* __restrict__ dst, int E) {
    int e = blockIdx.x * blockDim.x + threadIdx.x;
    if (e < E) {
        atomicAdd(&g_outdeg[src[e]], 1);
        atomicAdd(&g_indeg [dst[e]], 1);
    }
}

__global__ void scan_block_kernel(int n) {           // grid=ceil(n/1024), block=1024
    __shared__ int sh[1024];
    const int tid = threadIdx.x;
    const int i = blockIdx.x * 1024 + tid;
    int v = (i < n) ? g_indeg[i] : 0;
    sh[tid] = v;
    __syncthreads();
#pragma unroll
    for (int off = 1; off < 1024; off <<= 1) {
        int t = (tid >= off) ? sh[tid - off] : 0;
        __syncthreads();
        sh[tid] += t;
        __syncthreads();
    }
    if (i < n) g_start[i] = sh[tid] - v;             // exclusive within block
    if (tid == 1023) g_bsum[blockIdx.x] = sh[1023];  // block total
}

__global__ void scan_bsums_kernel(int nb) {          // 1 block, 128 threads
    __shared__ int sh[128];
    const int tid = threadIdx.x;
    int v = (tid < nb) ? g_bsum[tid] : 0;
    sh[tid] = v;
    __syncthreads();
#pragma unroll
    for (int off = 1; off < 128; off <<= 1) {
        int t = (tid >= off) ? sh[tid - off] : 0;
        __syncthreads();
        sh[tid] += t;
        __syncthreads();
    }
    if (tid < nb) g_bsum[tid] = sh[tid] - v;         // exclusive block offsets
}

__global__ void scan_add_kernel(int n) {             // block=1024 (i>>10 match)
    int i = blockIdx.x * 1024 + threadIdx.x;
    if (i < n) {
        int s = g_start[i] + g_bsum[i >> 10];
        g_start[i]  = s;
        g_cursor[i] = s;
    }
}

__global__ void fill_kernel(const int* __restrict__ src,
                            const int* __restrict__ dst,
                            const float* __restrict__ ew, int E) {
    int e = blockIdx.x * blockDim.x + threadIdx.x;
    if (e < E) {
        int d = dst[e];
        int slot = atomicAdd(&g_cursor[d], 1);
        g_edge[slot] = make_int2(src[e], __float_as_int(ew[e]));
    }
}

// W[256][128] f32 -> transposed split bf16 Wt[n][k]
__global__ void wsplit_kernel(const float* __restrict__ W) {
    int idx = blockIdx.x * blockDim.x + threadIdx.x;
    if (idx < IN_FEATS * OUT_FEATS) {
        int k = idx >> 7;            // 0..255
        int n = idx & 127;           // 0..127
        float x = W[idx];
        __nv_bfloat16 hi = __float2bfloat16(x);
        float lo = x - __bfloat162float(hi);
        g_Wt_hi[n * IN_FEATS + k] = hi;
        g_Wt_lo[n * IN_FEATS + k] = __float2bfloat16(lo);
    }
}

// ======================= split-bf16 mma.sync GEMM ===========================
// CTA: 128x128 tile, 8 warps (2m x 4n), warp tile 64x32, K chunks of 64.
// Smem tiles padded to 72 elems/row -> conflict-free 32-bit fragment LDS.
#define KC       64
#define NCHUNK   (IN_FEATS / KC)     // 4
#define TSTRIDE  72                  // elements per smem row (pad 64+8)
#define TROWB    (TSTRIDE * 2)       // 144 bytes
#define TILE_B   (128 * TROWB)       // 18432 bytes per tile
#define SM_AHI   0
#define SM_ALO   (SM_AHI + TILE_B)
#define SM_BHI   (SM_ALO + TILE_B)
#define SM_BLO   (SM_BHI + TILE_B)
#define SM_TOT   (SM_BLO + TILE_B)   // 73728 bytes

__device__ __forceinline__ uint32_t pack2bf(float a, float b) {
    __nv_bfloat162 t = __floats2bfloat162_rn(a, b);
    return *reinterpret_cast<uint32_t*>(&t);
}

#define MMA_BF16(c, a, b)                                                     \
    asm volatile(                                                             \
        "mma.sync.aligned.m16n8k16.row.col.f32.bf16.bf16.f32 "                \
        "{%0,%1,%2,%3}, {%4,%5,%6,%7}, {%8,%9}, {%0,%1,%2,%3};"               \
        : "+f"((c)[0]), "+f"((c)[1]), "+f"((c)[2]), "+f"((c)[3])              \
        : "r"((a)[0]), "r"((a)[1]), "r"((a)[2]), "r"((a)[3]),                 \
          "r"((b)[0]), "r"((b)[1]))

__global__ __launch_bounds__(256)
void gemm_mma_kernel(const float* __restrict__ feat, int M) {
    extern __shared__ __align__(16) char dsm[];
    const int tid  = threadIdx.x;
    const int lane = tid & 31;
    const int w    = tid >> 5;
    const int g    = lane >> 2;       // 0..7
    const int t    = lane & 3;        // 0..3
    const int m0   = (w >> 2) * 64;   // warp m-offset in tile
    const int n0   = (w & 3) * 32;    // warp n-offset in tile
    const int row0 = blockIdx.x * 128;

    // staging assignment: thread covers (row = tid/2, khalf = (tid&1)*32)
    const int srow = tid >> 1;
    const int skh  = (tid & 1) * 32;
    const bool rok = (row0 + srow) < M;
    float ascale = 0.0f;
    if (rok) {
        int dg = g_outdeg[row0 + srow];
        ascale = rsqrtf((float)(dg > 0 ? dg : 1));
    }

    float acc[4][4][4];
#pragma unroll
    for (int i = 0; i < 4; ++i)
#pragma unroll
        for (int j = 0; j < 4; ++j)
#pragma unroll
            for (int q = 0; q < 4; ++q) acc[i][j][q] = 0.0f;

#pragma unroll 1
    for (int c = 0; c < NCHUNK; ++c) {
        // ---- stage A (f32 -> bf16 hi/lo with ascale) ----
        {
            const float* ap = feat + (size_t)(row0 + srow) * IN_FEATS + c * KC + skh;
            char* dsthi = dsm + SM_AHI + srow * TROWB + skh * 2;
            char* dstlo = dsm + SM_ALO + srow * TROWB + skh * 2;
#pragma unroll
            for (int i = 0; i < 4; ++i) {            // 4 x 8 elems
                float4 f0 = make_float4(0.f, 0.f, 0.f, 0.f);
                float4 f1 = make_float4(0.f, 0.f, 0.f, 0.f);
                if (rok) {
                    f0 = __ldg((const float4*)(ap + i * 8));
                    f1 = __ldg((const float4*)(ap + i * 8 + 4));
                }
                f0.x *= ascale; f0.y *= ascale; f0.z *= ascale; f0.w *= ascale;
                f1.x *= ascale; f1.y *= ascale; f1.z *= ascale; f1.w *= ascale;
                float h[8] = {f0.x, f0.y, f0.z, f0.w, f1.x, f1.y, f1.z, f1.w};
                uint4 hv, lv;
                float hi0, hi1;
                hi0 = __bfloat162float(__float2bfloat16(h[0]));
                hi1 = __bfloat162float(__float2bfloat16(h[1]));
                hv.x = pack2bf(h[0], h[1]); lv.x = pack2bf(h[0]-hi0, h[1]-hi1);
                hi0 = __bfloat162float(__float2bfloat16(h[2]));
                hi1 = __bfloat162float(__float2bfloat16(h[3]));
                hv.y = pack2bf(h[2], h[3]); lv.y = pack2bf(h[2]-hi0, h[3]-hi1);
                hi0 = __bfloat162float(__float2bfloat16(h[4]));
                hi1 = __bfloat162float(__float2bfloat16(h[5]));
                hv.z = pack2bf(h[4], h[5]); lv.z = pack2bf(h[4]-hi0, h[5]-hi1);
                hi0 = __bfloat162float(__float2bfloat16(h[6]));
                hi1 = __bfloat162float(__float2bfloat16(h[7]));
                hv.w = pack2bf(h[6], h[7]); lv.w = pack2bf(h[6]-hi0, h[7]-hi1);
                *(uint4*)(dsthi + i * 16) = hv;
                *(uint4*)(dstlo + i * 16) = lv;
            }
        }
        // ---- stage B (preconverted bf16; Wt row n = srow) ----
        {
            const __nv_bfloat16* bh = g_Wt_hi + srow * IN_FEATS + c * KC + skh;
            const __nv_bfloat16* bl = g_Wt_lo + srow * IN_FEATS + c * KC + skh;
            char* dsthi = dsm + SM_BHI + srow * TROWB + skh * 2;
            char* dstlo = dsm + SM_BLO + srow * TROWB + skh * 2;
#pragma unroll
            for (int i = 0; i < 4; ++i) {            // 4 x uint4 = 32 bf16
                *(uint4*)(dsthi + i * 16) = __ldg((const uint4*)(bh + i * 8));
                *(uint4*)(dstlo + i * 16) = __ldg((const uint4*)(bl + i * 8));
            }
        }
        __syncthreads();

        // ---- compute: 4 k16 steps ----
#pragma unroll
        for (int ks = 0; ks < 4; ++ks) {
            uint32_t ah[4][4], al[4][4];
#pragma unroll
            for (int mf = 0; mf < 4; ++mf) {
                int ro = (m0 + mf * 16 + g) * TROWB + ks * 32 + t * 4;
                ah[mf][0] = *(const uint32_t*)(dsm + SM_AHI + ro);
                ah[mf][1] = *(const uint32_t*)(dsm + SM_AHI + ro + 8 * TROWB);
                ah[mf][2] = *(const uint32_t*)(dsm + SM_AHI + ro + 16);
                ah[mf][3] = *(const uint32_t*)(dsm + SM_AHI + ro + 8 * TROWB + 16);
                al[mf][0] = *(const uint32_t*)(dsm + SM_ALO + ro);
                al[mf][1] = *(const uint32_t*)(dsm + SM_ALO + ro + 8 * TROWB);
                al[mf][2] = *(const uint32_t*)(dsm + SM_ALO + ro + 16);
                al[mf][3] = *(const uint32_t*)(dsm + SM_ALO + ro + 8 * TROWB + 16);
            }
            uint32_t bh[4][2], bl[4][2];
#pragma unroll
            for (int nf = 0; nf < 4; ++nf) {
                int no = (n0 + nf * 8 + g) * TROWB + ks * 32 + t * 4;
                bh[nf][0] = *(const uint32_t*)(dsm + SM_BHI + no);
                bh[nf][1] = *(const uint32_t*)(dsm + SM_BHI + no + 16);
                bl[nf][0] = *(const uint32_t*)(dsm + SM_BLO + no);
                bl[nf][1] = *(const uint32_t*)(dsm + SM_BLO + no + 16);
            }
#pragma unroll
            for (int mf = 0; mf < 4; ++mf)
#pragma unroll
                for (int nf = 0; nf < 4; ++nf) {
                    MMA_BF16(acc[mf][nf], ah[mf], bh[nf]);
                    MMA_BF16(acc[mf][nf], ah[mf], bl[nf]);
                    MMA_BF16(acc[mf][nf], al[mf], bh[nf]);
                }
        }
        __syncthreads();
    }

    // ---- epilogue: tanh -> g_h ----
#pragma unroll
    for (int mf = 0; mf < 4; ++mf) {
        int r0g = row0 + m0 + mf * 16 + g;
        int r1g = r0g + 8;
#pragma unroll
        for (int nf = 0; nf < 4; ++nf) {
            int col = n0 + nf * 8 + t * 2;
            if (r0g < M) {
                float2 o;
                o.x = tanhf(acc[mf][nf][0]);
                o.y = tanhf(acc[mf][nf][1]);
                *(float2*)(g_h + (size_t)r0g * OUT_FEATS + col) = o;
            }
            if (r1g < M) {
                float2 o;
                o.x = tanhf(acc[mf][nf][2]);
                o.y = tanhf(acc[mf][nf][3]);
                *(float2*)(g_h + (size_t)r1g * OUT_FEATS + col) = o;
            }
        }
    }
}

// ======================= aggregate ==========================================
// One warp per dst node, lane owns one float4. 2-way unrolled gather.
__global__ __launch_bounds__(256)
void aggregate_kernel(float* __restrict__ out, int N) {
    const int lane = threadIdx.x & 31;
    const int n = blockIdx.x * (blockDim.x >> 5) + (threadIdx.x >> 5);
    if (n >= N) return;

    const int begin = g_start[n];
    const int cnt   = g_indeg[n];

    float4 acc = make_float4(0.f, 0.f, 0.f, 0.f);
    const float4* h4 = (const float4*)g_h;

    int j = 0;
    for (; j + 2 <= cnt; j += 2) {
        int2 e0 = g_edge[begin + j];
        int2 e1 = g_edge[begin + j + 1];
        float4 v0 = __ldg(h4 + (size_t)e0.x * (OUT_FEATS / 4) + lane);
        float4 v1 = __ldg(h4 + (size_t)e1.x * (OUT_FEATS / 4) + lane);
        float w0 = __int_as_float(e0.y);
        float w1 = __int_as_float(e1.y);
        acc.x = fmaf(v0.x, w0, acc.x); acc.y = fmaf(v0.y, w0, acc.y);
        acc.z = fmaf(v0.z, w0, acc.z); acc.w = fmaf(v0.w, w0, acc.w);
        acc.x = fmaf(v1.x, w1, acc.x); acc.y = fmaf(v1.y, w1, acc.y);
        acc.z = fmaf(v1.z, w1, acc.z); acc.w = fmaf(v1.w, w1, acc.w);
    }
    if (j < cnt) {
        int2 e0 = g_edge[begin + j];
        float4 v0 = __ldg(h4 + (size_t)e0.x * (OUT_FEATS / 4) + lane);
        float w0 = __int_as_float(e0.y);
        acc.x = fmaf(v0.x, w0, acc.x); acc.y = fmaf(v0.y, w0, acc.y);
        acc.z = fmaf(v0.z, w0, acc.z); acc.w = fmaf(v0.w, w0, acc.w);
    }

    const float sc = rsqrtf((float)(cnt > 0 ? cnt : 1));
    acc.x *= sc; acc.y *= sc; acc.z *= sc; acc.w *= sc;
    ((float4*)(out + (size_t)n * OUT_FEATS))[lane] = acc;
}

// ---------------------------------------------------------------------------
extern "C" void kernel_launch(void* const* d_in, const int* in_sizes, int n_in,
                              void* d_out, int out_size) {
    const float* feat = (const float*)d_in[0];
    const float* W    = (const float*)d_in[1];
    const float* ew   = (const float*)d_in[2];
    const int*   src  = (const int*)d_in[3];   // int32 on device
    const int*   dst  = (const int*)d_in[4];
    float*       out  = (float*)d_out;

    const int M = in_sizes[0] / IN_FEATS;   // 100000
    const int E = in_sizes[2];              // 1600000
    const int nb = (M + 1023) / 1024;       // 98 scan blocks

    cudaFuncSetAttribute(gemm_mma_kernel,
                         cudaFuncAttributeMaxDynamicSharedMemorySize, SM_TOT);

    zero_deg_kernel<<<(M + 255) / 256, 256>>>(M);
    degree_kernel<<<(E + 255) / 256, 256>>>(src, dst, E);
    scan_block_kernel<<<nb, 1024>>>(M);
    scan_bsums_kernel<<<1, 128>>>(nb);
    scan_add_kernel<<<nb, 1024>>>(M);
    fill_kernel<<<(E + 255) / 256, 256>>>(src, dst, ew, E);
    wsplit_kernel<<<(IN_FEATS * OUT_FEATS + 255) / 256, 256>>>(W);
    gemm_mma_kernel<<<(M + 127) / 128, 256, SM_TOT>>>(feat, M);
    {
        const int warps_per_block = 256 / 32;
        const int blocks = (M + warps_per_block - 1) / warps_per_block;
        aggregate_kernel<<<blocks, 256>>>(out, M);
    }
}